// round 14
// baseline (speedup 1.0000x reference)
#include <cuda_runtime.h>
#include <cuda_bf16.h>
#include <cstdint>

// ScaledDotProductAttention B=2,H=16,S=2048,D=64 fp32, key-padding mask.
// Warp-level HMMA (mma.sync bf16) flash attention; fp32 emulated via
// bf16 hi/lo 3-term split (precision floor: 2-term variants measured at
// rel_err ~1.1e-3 > 1e-3). Masked keys COMPACTED away during a single
// fused gather+split prologue (per-block bitmap scan). 128-thread CTAs
// (BM=64, BK=32) at 4 CTAs/SM; double-buffered cp.async staging,
// ldmatrix.x4, softmax pipelined under GEMM1. Pad bias on final tile only.

#define B_BATCH 2
#define H_HEADS 16
#define S_LEN   2048
#define DH      64
#define BM      64          // q rows per CTA (16 per warp, 4 warps)
#define BK      32          // keys per tile
#define MASK_N  (B_BATCH * S_LEN)
#define SROW    72          // smem row stride in bf16 elems (144B, conflict-free)
#define KV_ELEMS (B_BATCH * H_HEADS * S_LEN * DH)

// smem: [buf][arr][row 32][SROW] bf16  (arr: 0=Khi 1=Klo 2=Vhi 3=Vlo)
#define ARR_BYTES  (BK * SROW * 2)          // 4608
#define BUF_BYTES  (4 * ARR_BYTES)          // 18432
#define MASK_OFF   (2 * BUF_BYTES)          // 36864
#define SMEM_BYTES (MASK_OFF + BK * 4)      // 36992

// ---------------- global buffers ----------------
__device__ __nv_bfloat16 gKhi[KV_ELEMS];
__device__ __nv_bfloat16 gKlo[KV_ELEMS];
__device__ __nv_bfloat16 gVhi[KV_ELEMS];
__device__ __nv_bfloat16 gVlo[KV_ELEMS];
__device__ int gN[B_BATCH];     // per batch: number of unmasked keys

// ---------------- helpers ----------------
__device__ __forceinline__ float fast_exp2(float x) {
    float y; asm("ex2.approx.ftz.f32 %0, %1;" : "=f"(y) : "f"(x)); return y;
}
__device__ __forceinline__ uint32_t cvt_bf16x2(float lo, float hi) {
    uint32_t d;
    asm("cvt.rn.bf16x2.f32 %0, %1, %2;" : "=r"(d) : "f"(hi), "f"(lo));
    return d;
}
// split (a,b) into packed bf16 hi pair + packed bf16 residual pair
__device__ __forceinline__ void split2(float a, float b, uint32_t& hi, uint32_t& lo) {
    hi = cvt_bf16x2(a, b);
    float ah = __uint_as_float(hi << 16);
    float bh = __uint_as_float(hi & 0xFFFF0000u);
    lo = cvt_bf16x2(a - ah, b - bh);
}
__device__ __forceinline__ uint32_t smem_u32(const void* p) {
    uint32_t a;
    asm("{ .reg .u64 t; cvta.to.shared.u64 t, %1; cvt.u32.u64 %0, t; }" : "=r"(a) : "l"(p));
    return a;
}
__device__ __forceinline__ void ldsm_x4(uint32_t addr, uint32_t& r0, uint32_t& r1,
                                        uint32_t& r2, uint32_t& r3) {
    asm volatile("ldmatrix.sync.aligned.m8n8.x4.shared.b16 {%0,%1,%2,%3}, [%4];"
                 : "=r"(r0), "=r"(r1), "=r"(r2), "=r"(r3) : "r"(addr));
}
__device__ __forceinline__ void ldsm_x4t(uint32_t addr, uint32_t& r0, uint32_t& r1,
                                         uint32_t& r2, uint32_t& r3) {
    asm volatile("ldmatrix.sync.aligned.m8n8.x4.trans.shared.b16 {%0,%1,%2,%3}, [%4];"
                 : "=r"(r0), "=r"(r1), "=r"(r2), "=r"(r3) : "r"(addr));
}
__device__ __forceinline__ void cp16(uint32_t dst, const void* src) {
    asm volatile("cp.async.cg.shared.global [%0], [%1], 16;" :: "r"(dst), "l"(src));
}
#define CP_COMMIT() asm volatile("cp.async.commit_group;" ::: "memory")
#define CP_WAIT0()  asm volatile("cp.async.wait_group 0;" ::: "memory")

#define MMA_BF16(c, a0, a1, a2, a3, b0, b1)                                      \
    asm volatile("mma.sync.aligned.m16n8k16.row.col.f32.bf16.bf16.f32 "          \
                 "{%0,%1,%2,%3}, {%4,%5,%6,%7}, {%8,%9}, {%0,%1,%2,%3};"         \
                 : "+f"((c)[0]), "+f"((c)[1]), "+f"((c)[2]), "+f"((c)[3])        \
                 : "r"(a0), "r"(a1), "r"(a2), "r"(a3), "r"(b0), "r"(b1))

// ---------------- fused prologue: mask scan + compacting gather + split ----------------
// 256 threads/block; block handles 16 consecutive compacted rows of one (b,h).
// Each block rebuilds the 2048-bit key bitmap for its batch (L2-resident reads),
// prefix-popcounts it, and selects its 16 source rows (n-th set bit).
__global__ __launch_bounds__(256)
void presplit_kernel(const float* __restrict__ K, const float* __restrict__ V,
                     const void* __restrict__ mraw)
{
    const int g   = blockIdx.x * 16;                        // first global row (b,h,r)
    const int bh  = g / S_LEN;
    const int r0b = g - bh * S_LEN;                         // first compacted row in bh
    const int b   = bh / H_HEADS;
    const int tid = threadIdx.x;

    __shared__ int not_i32, not_f32;
    __shared__ uint32_t bitmap[64];
    __shared__ int cum[65];          // cum[w] = popc of words [0,w)
    __shared__ int srcrow[16];
    __shared__ int s_nvalid;

    const unsigned int*  w32 = (const unsigned int*)mraw;
    const unsigned char* w8  = (const unsigned char*)mraw;

    if (tid == 0) { not_i32 = 0; not_f32 = 0; }
    __syncthreads();
#pragma unroll
    for (int r = 0; r < 4; r++) {   // dtype detect over first 4096 bytes (in-bounds always)
        unsigned int w = w32[tid + 256 * r];
        if (w > 1u)                       atomicOr(&not_i32, 1);
        if (w != 0u && w != 0x3F800000u)  atomicOr(&not_f32, 1);
    }
    __syncthreads();
    const bool is_word = (not_i32 == 0) || (not_f32 == 0);

    // build this batch's bitmap: thread t (t<64) builds word t (keys 32t..32t+31)
    if (tid < 64) {
        uint32_t bits = 0;
        const int kbase = b * S_LEN + 32 * tid;
#pragma unroll
        for (int j = 0; j < 32; j++) {
            bool f = is_word ? (w32[kbase + j] != 0u) : (w8[kbase + j] != 0u);
            bits |= (uint32_t)f << j;
        }
        bitmap[tid] = bits;
    }
    __syncthreads();
    if (tid == 0) {
        int acc = 0;
        for (int w = 0; w < 64; w++) { cum[w] = acc; acc += __popc(bitmap[w]); }
        cum[64] = acc;
        s_nvalid = acc;
        if (r0b == 0 && (bh % H_HEADS) == 0) gN[b] = acc;   // one writer per batch
    }
    __syncthreads();
    const int nvalid = s_nvalid;
    const int padrows = (nvalid + BK - 1) & ~(BK - 1);
    if (r0b >= padrows) return;

    // resolve the 16 source rows (n-th set bit selection)
    if (tid < 16) {
        int r = r0b + tid;
        int src = -1;
        if (r < nvalid) {
            int w = 0;
            while (cum[w + 1] <= r) w++;                    // cum[w] <= r < cum[w+1]
            int n = r - cum[w];                             // 0-indexed within word
            uint32_t word = bitmap[w];
            for (int i = 0; i < n; i++) word &= word - 1;   // drop n lowest set bits
            src = 32 * w + (__ffs(word) - 1);
        }
        srcrow[tid] = src;
    }
    __syncthreads();

    // gather + split: thread handles float4 c4 of local row rl
    const int rl  = tid >> 4;
    const int c4  = tid & 15;
    const int src = srcrow[rl];

    const size_t dsti = (size_t)(g + rl) * 16 + c4;         // uint2 index
    uint2* Khi2 = (uint2*)gKhi; uint2* Klo2 = (uint2*)gKlo;
    uint2* Vhi2 = (uint2*)gVhi; uint2* Vlo2 = (uint2*)gVlo;

    if (src >= 0) {
        const size_t srci = ((size_t)bh * S_LEN + src) * 16 + c4;
        float4 k = ((const float4*)K)[srci];
        uint32_t h0, l0, h1, l1;
        split2(k.x, k.y, h0, l0);
        split2(k.z, k.w, h1, l1);
        Khi2[dsti] = make_uint2(h0, h1);
        Klo2[dsti] = make_uint2(l0, l1);
        float4 v = ((const float4*)V)[srci];
        split2(v.x, v.y, h0, l0);
        split2(v.z, v.w, h1, l1);
        Vhi2[dsti] = make_uint2(h0, h1);
        Vlo2[dsti] = make_uint2(l0, l1);
    } else {
        uint2 z = make_uint2(0u, 0u);
        Khi2[dsti] = z; Klo2[dsti] = z;
        Vhi2[dsti] = z; Vlo2[dsti] = z;
    }
}

// ---------------- main kernel ----------------
__global__ __launch_bounds__(128, 4)
void flash_attn_hmma(const float* __restrict__ Q, float* __restrict__ O)
{
    extern __shared__ __align__(16) char sm[];
    const uint32_t sb = smem_u32(sm);
    float* smask = (float*)(sm + MASK_OFF);            // [32] pad bias (last tile only)

    const int tid   = threadIdx.x;
    const int wid   = tid >> 5;
    const int lane  = tid & 31;
    const int group = lane >> 2;
    const int tig   = lane & 3;
    const int lg    = lane >> 3;      // 0..3: ldmatrix lane-group
    const int lr    = lane & 7;

    const int qt = blockIdx.x & (S_LEN / BM - 1);      // 32 q-tiles/head
    const int bh = blockIdx.x >> 5;
    const int b  = bh / H_HEADS;

    const int nvalid = gN[b];
    const int ntiles = (nvalid + BK - 1) / BK;

    const size_t kvbase = (size_t)bh * S_LEN * DH;
    const __nv_bfloat16* garr[4] = { gKhi + kvbase, gKlo + kvbase,
                                     gVhi + kvbase, gVlo + kvbase };

    // ---- Q fragments (hi/lo), loaded once ----
    const float QSC = 0.125f * 1.44269504088896340736f;   // 1/sqrt(64) * log2(e)
    uint32_t qhi[4][4], qlo[4][4];
    {
        const float* Qb = Q + ((size_t)bh * S_LEN + (size_t)qt * BM + wid * 16) * DH;
        const int r0 = group, r1 = group + 8;
#pragma unroll
        for (int k = 0; k < 4; k++) {
            int c0 = 16 * k + 2 * tig, c1 = c0 + 8;
            float2 f;
            f = *(const float2*)(Qb + r0 * DH + c0);
            split2(f.x * QSC, f.y * QSC, qhi[k][0], qlo[k][0]);
            f = *(const float2*)(Qb + r1 * DH + c0);
            split2(f.x * QSC, f.y * QSC, qhi[k][1], qlo[k][1]);
            f = *(const float2*)(Qb + r0 * DH + c1);
            split2(f.x * QSC, f.y * QSC, qhi[k][2], qlo[k][2]);
            f = *(const float2*)(Qb + r1 * DH + c1);
            split2(f.x * QSC, f.y * QSC, qhi[k][3], qlo[k][3]);
        }
    }

    float o[8][4];
#pragma unroll
    for (int j = 0; j < 8; j++)
#pragma unroll
        for (int i = 0; i < 4; i++) o[j][i] = 0.f;
    float l0 = 0.f, l1 = 0.f;

    const float CSH = 12.0f * 1.44269504088896340736f;  // static shift, exp2 domain

    // ldmatrix.x4 per-lane byte offsets (within an array tile)
    const uint32_t koff = (uint32_t)(((8 * (lg >> 1) + lr) * SROW + 8 * (lg & 1)) * 2);
    const uint32_t voff = (uint32_t)(((8 * (lg & 1) + lr) * SROW + 8 * (lg >> 1)) * 2);

    // ---- pad-bias for the final tile, written once ----
    if (tid < BK)
        smask[tid] = ((ntiles - 1) * BK + tid < nvalid) ? 0.f : -3.0e38f;

    // ---- stage tile 0 (8 cp.async per thread: 2 per array) ----
#pragma unroll
    for (int arr = 0; arr < 4; arr++) {
#pragma unroll
        for (int ii = 0; ii < 2; ii++) {
            int idx = tid + 128 * ii;                 // 16B-chunk index 0..255
            int row = idx >> 3, ch = idx & 7;
            cp16(sb + arr * ARR_BYTES + row * 144 + ch * 16,
                 garr[arr] + row * 64 + ch * 8);
        }
    }
    CP_COMMIT();

    for (int t = 0; t < ntiles; t++) {
        const int buf = t & 1;
        CP_WAIT0();
        __syncthreads();

        // ---- prefetch tile t+1 into buf^1 ----
        if (t + 1 < ntiles) {
            const int nb = buf ^ 1;
            const size_t toff = (size_t)(t + 1) * BK * DH;
#pragma unroll
            for (int arr = 0; arr < 4; arr++) {
#pragma unroll
                for (int ii = 0; ii < 2; ii++) {
                    int idx = tid + 128 * ii;
                    int row = idx >> 3, ch = idx & 7;
                    cp16(sb + nb * BUF_BYTES + arr * ARR_BYTES + row * 144 + ch * 16,
                         garr[arr] + toff + row * 64 + ch * 8);
                }
            }
        }
        CP_COMMIT();

        const uint32_t aKhi = sb + buf * BUF_BYTES;
        const uint32_t aKlo = aKhi + ARR_BYTES;
        const uint32_t aVhi = aKlo + ARR_BYTES;
        const uint32_t aVlo = aVhi + ARR_BYTES;
        const bool last = (t == ntiles - 1);

        float s[4][4];

        // GEMM1 for one key-16-block jp (0..1): S[:, 16jp..16jp+15]
#define GEMM1_JP(jp)                                                                  \
        do {                                                                          \
            _Pragma("unroll")                                                         \
            for (int i = 0; i < 4; i++) { s[2*(jp)][i] = 0.f; s[2*(jp)+1][i] = 0.f; } \
            uint32_t jb = koff + (uint32_t)(16 * (jp) * SROW * 2);                    \
            _Pragma("unroll")                                                         \
            for (int k = 0; k < 4; k++) {                                             \
                uint32_t boff = jb + (uint32_t)(16 * k * 2);                          \
                uint32_t h0, h1, h2, h3, x0, x1, x2, x3;                              \
                ldsm_x4(aKhi + boff, h0, h1, h2, h3);                                 \
                ldsm_x4(aKlo + boff, x0, x1, x2, x3);                                 \
                MMA_BF16(s[2*(jp)],   qhi[k][0], qhi[k][1], qhi[k][2], qhi[k][3], h0, h1); \
                MMA_BF16(s[2*(jp)+1], qhi[k][0], qhi[k][1], qhi[k][2], qhi[k][3], h2, h3); \
                MMA_BF16(s[2*(jp)],   qhi[k][0], qhi[k][1], qhi[k][2], qhi[k][3], x0, x1); \
                MMA_BF16(s[2*(jp)+1], qhi[k][0], qhi[k][1], qhi[k][2], qhi[k][3], x2, x3); \
                MMA_BF16(s[2*(jp)],   qlo[k][0], qlo[k][1], qlo[k][2], qlo[k][3], h0, h1); \
                MMA_BF16(s[2*(jp)+1], qlo[k][0], qlo[k][1], qlo[k][2], qlo[k][3], h2, h3); \
            }                                                                         \
        } while (0)

        GEMM1_JP(0);

#pragma unroll
        for (int k = 0; k < 2; k++) {
            // ---- softmax for key-step k (keys 16k..16k+15) ----
            uint32_t phi[4], plo[4];
            {
                float b00, b01, b10, b11;
                if (last) {
                    b00 = smask[16 * k + 2 * tig]         - CSH;
                    b01 = smask[16 * k + 2 * tig + 1]     - CSH;
                    b10 = smask[16 * k + 8 + 2 * tig]     - CSH;
                    b11 = smask[16 * k + 8 + 2 * tig + 1] - CSH;
                } else {
                    b00 = b01 = b10 = b11 = -CSH;
                }
                float p00 = fast_exp2(s[2*k][0] + b00);
                float p01 = fast_exp2(s[2*k][1] + b01);
                float p02 = fast_exp2(s[2*k][2] + b00);
                float p03 = fast_exp2(s[2*k][3] + b01);
                float p10 = fast_exp2(s[2*k+1][0] + b10);
                float p11 = fast_exp2(s[2*k+1][1] + b11);
                float p12 = fast_exp2(s[2*k+1][2] + b10);
                float p13 = fast_exp2(s[2*k+1][3] + b11);
                l0 += (p00 + p01) + (p10 + p11);
                l1 += (p02 + p03) + (p12 + p13);
                split2(p00, p01, phi[0], plo[0]);
                split2(p02, p03, phi[1], plo[1]);
                split2(p10, p11, phi[2], plo[2]);
                split2(p12, p13, phi[3], plo[3]);
            }

            // ---- GEMM1 for the second key block overlaps the softmax chains ----
            if (k == 0) GEMM1_JP(1);

            // ---- GEMM2 step k: O += P[:,16k..16k+15] x V[16k..16k+15, :] ----
#pragma unroll
            for (int jp = 0; jp < 4; jp++) {
                uint32_t boff = voff + (uint32_t)(16 * jp * 2)
                              + (uint32_t)(16 * k * SROW * 2);
                uint32_t h0, h1, h2, h3, x0, x1, x2, x3;
                ldsm_x4t(aVhi + boff, h0, h1, h2, h3);
                ldsm_x4t(aVlo + boff, x0, x1, x2, x3);
                MMA_BF16(o[2*jp],   phi[0], phi[1], phi[2], phi[3], h0, h1);
                MMA_BF16(o[2*jp+1], phi[0], phi[1], phi[2], phi[3], h2, h3);
                MMA_BF16(o[2*jp],   phi[0], phi[1], phi[2], phi[3], x0, x1);
                MMA_BF16(o[2*jp+1], phi[0], phi[1], phi[2], phi[3], x2, x3);
                MMA_BF16(o[2*jp],   plo[0], plo[1], plo[2], plo[3], h0, h1);
                MMA_BF16(o[2*jp+1], plo[0], plo[1], plo[2], plo[3], h2, h3);
            }
        }
#undef GEMM1_JP
    }

    // ---- epilogue ----
    l0 += __shfl_xor_sync(0xFFFFFFFFu, l0, 1);
    l0 += __shfl_xor_sync(0xFFFFFFFFu, l0, 2);
    l1 += __shfl_xor_sync(0xFFFFFFFFu, l1, 1);
    l1 += __shfl_xor_sync(0xFFFFFFFFu, l1, 2);
    float inv0 = 1.f / fmaxf(l0, 1e-35f);
    float inv1 = 1.f / fmaxf(l1, 1e-35f);

    float* Ob = O + ((size_t)bh * S_LEN + (size_t)qt * BM + wid * 16) * DH;
    const int r0 = group, r1 = group + 8;
#pragma unroll
    for (int j = 0; j < 8; j++) {
        int c = 8 * j + 2 * tig;
        *(float2*)(Ob + r0 * DH + c) = make_float2(o[j][0] * inv0, o[j][1] * inv0);
        *(float2*)(Ob + r1 * DH + c) = make_float2(o[j][2] * inv1, o[j][3] * inv1);
    }
}

extern "C" void kernel_launch(void* const* d_in, const int* in_sizes, int n_in,
                              void* d_out, int out_size)
{
    (void)in_sizes; (void)n_in; (void)out_size;
    const float* Q = (const float*)d_in[0];
    const float* K = (const float*)d_in[1];
    const float* V = (const float*)d_in[2];
    const void*  M = d_in[3];
    float* O = (float*)d_out;

    static int smem_set = 0;
    if (!smem_set) {
        cudaFuncSetAttribute(flash_attn_hmma,
                             cudaFuncAttributeMaxDynamicSharedMemorySize, SMEM_BYTES);
        smem_set = 1;
    }

    presplit_kernel<<<B_BATCH * H_HEADS * S_LEN / 16, 256>>>(K, V, M);
    flash_attn_hmma<<<B_BATCH * H_HEADS * (S_LEN / BM), 128, SMEM_BYTES>>>(Q, O);
}

// round 15
// speedup vs baseline: 1.3281x; 1.3281x over previous
#include <cuda_runtime.h>
#include <cuda_bf16.h>
#include <cstdint>

// ScaledDotProductAttention B=2,H=16,S=2048,D=64 fp32, key-padding mask.
// Warp-level HMMA (mma.sync bf16) flash attention; fp32 emulated via
// bf16 hi/lo 3-term split. Masked keys are COMPACTED away in the prologue
// (per-batch prefix sum -> gather), halving the GEMM work. 128-thread CTAs
// (BM=64, BK=32) at 4 CTAs/SM; double-buffered cp.async staging, ldmatrix.x4,
// softmax pipelined under GEMM1. Pad bias applied only on the final tile.
// [R15: restored R12 configuration — measured optimum 137.8us.]

#define B_BATCH 2
#define H_HEADS 16
#define S_LEN   2048
#define DH      64
#define BM      64          // q rows per CTA (16 per warp, 4 warps)
#define BK      32          // keys per tile
#define MASK_N  (B_BATCH * S_LEN)
#define SROW    72          // smem row stride in bf16 elems (144B, conflict-free)
#define KV_ELEMS (B_BATCH * H_HEADS * S_LEN * DH)

// smem: [buf][arr][row 32][SROW] bf16  (arr: 0=Khi 1=Klo 2=Vhi 3=Vlo)
#define ARR_BYTES  (BK * SROW * 2)          // 4608
#define BUF_BYTES  (4 * ARR_BYTES)          // 18432
#define MASK_OFF   (2 * BUF_BYTES)          // 36864
#define SMEM_BYTES (MASK_OFF + BK * 4)      // 36992

// ---------------- global buffers ----------------
__device__ __nv_bfloat16 gKhi[KV_ELEMS];
__device__ __nv_bfloat16 gKlo[KV_ELEMS];
__device__ __nv_bfloat16 gVhi[KV_ELEMS];
__device__ __nv_bfloat16 gVlo[KV_ELEMS];
__device__ int gPerm[MASK_N];   // per batch: compacted key indices
__device__ int gN[B_BATCH];     // per batch: number of unmasked keys

// ---------------- helpers ----------------
__device__ __forceinline__ float fast_exp2(float x) {
    float y; asm("ex2.approx.ftz.f32 %0, %1;" : "=f"(y) : "f"(x)); return y;
}
__device__ __forceinline__ uint32_t cvt_bf16x2(float lo, float hi) {
    uint32_t d;
    asm("cvt.rn.bf16x2.f32 %0, %1, %2;" : "=r"(d) : "f"(hi), "f"(lo));
    return d;
}
// split (a,b) into packed bf16 hi pair + packed bf16 residual pair
__device__ __forceinline__ void split2(float a, float b, uint32_t& hi, uint32_t& lo) {
    hi = cvt_bf16x2(a, b);
    float ah = __uint_as_float(hi << 16);
    float bh = __uint_as_float(hi & 0xFFFF0000u);
    lo = cvt_bf16x2(a - ah, b - bh);
}
__device__ __forceinline__ uint32_t smem_u32(const void* p) {
    uint32_t a;
    asm("{ .reg .u64 t; cvta.to.shared.u64 t, %1; cvt.u32.u64 %0, t; }" : "=r"(a) : "l"(p));
    return a;
}
__device__ __forceinline__ void ldsm_x4(uint32_t addr, uint32_t& r0, uint32_t& r1,
                                        uint32_t& r2, uint32_t& r3) {
    asm volatile("ldmatrix.sync.aligned.m8n8.x4.shared.b16 {%0,%1,%2,%3}, [%4];"
                 : "=r"(r0), "=r"(r1), "=r"(r2), "=r"(r3) : "r"(addr));
}
__device__ __forceinline__ void ldsm_x4t(uint32_t addr, uint32_t& r0, uint32_t& r1,
                                         uint32_t& r2, uint32_t& r3) {
    asm volatile("ldmatrix.sync.aligned.m8n8.x4.trans.shared.b16 {%0,%1,%2,%3}, [%4];"
                 : "=r"(r0), "=r"(r1), "=r"(r2), "=r"(r3) : "r"(addr));
}
__device__ __forceinline__ void cp16(uint32_t dst, const void* src) {
    asm volatile("cp.async.cg.shared.global [%0], [%1], 16;" :: "r"(dst), "l"(src));
}
#define CP_COMMIT() asm volatile("cp.async.commit_group;" ::: "memory")
#define CP_WAIT0()  asm volatile("cp.async.wait_group 0;" ::: "memory")

#define MMA_BF16(c, a0, a1, a2, a3, b0, b1)                                      \
    asm volatile("mma.sync.aligned.m16n8k16.row.col.f32.bf16.bf16.f32 "          \
                 "{%0,%1,%2,%3}, {%4,%5,%6,%7}, {%8,%9}, {%0,%1,%2,%3};"         \
                 : "+f"((c)[0]), "+f"((c)[1]), "+f"((c)[2]), "+f"((c)[3])        \
                 : "r"(a0), "r"(a1), "r"(a2), "r"(a3), "r"(b0), "r"(b1))

// ---------------- compaction: mask detect + per-batch prefix sum ----------------
// grid = B_BATCH blocks x 1024 threads; thread t handles keys 2t, 2t+1.
__global__ __launch_bounds__(1024)
void compact_kernel(const void* __restrict__ mraw)
{
    const int b = blockIdx.x;
    const unsigned int*  w32 = (const unsigned int*)mraw;
    const unsigned char* w8  = (const unsigned char*)mraw;

    __shared__ int not_i32, not_f32;
    __shared__ int wsum[32];
    if (threadIdx.x == 0) { not_i32 = 0; not_f32 = 0; }
    __syncthreads();
    {   // dtype detection over first 4096 bytes (in-bounds for every encoding)
        unsigned int w = w32[threadIdx.x];
        if (w > 1u)                       atomicOr(&not_i32, 1);
        if (w != 0u && w != 0x3F800000u)  atomicOr(&not_f32, 1);
    }
    __syncthreads();
    const bool is_word = (not_i32 == 0) || (not_f32 == 0);

    const int i0 = 2 * threadIdx.x, i1 = i0 + 1;       // key indices within batch
    const int g0 = b * S_LEN + i0, g1 = g0 + 1;
    int f0 = is_word ? (w32[g0] != 0u) : (w8[g0] != 0u);
    int f1 = is_word ? (w32[g1] != 0u) : (w8[g1] != 0u);
    int val = f0 + f1;

    // intra-warp inclusive scan
    const int lane = threadIdx.x & 31, wid = threadIdx.x >> 5;
    int incl = val;
#pragma unroll
    for (int d = 1; d < 32; d <<= 1) {
        int n = __shfl_up_sync(0xFFFFFFFFu, incl, d);
        if (lane >= d) incl += n;
    }
    if (lane == 31) wsum[wid] = incl;
    __syncthreads();
    if (wid == 0) {
        int v = wsum[lane];
        int ws = v;
#pragma unroll
        for (int d = 1; d < 32; d <<= 1) {
            int n = __shfl_up_sync(0xFFFFFFFFu, ws, d);
            if (lane >= d) ws += n;
        }
        wsum[lane] = ws - v;                           // exclusive warp base
    }
    __syncthreads();
    int base = wsum[wid] + incl - val;                 // exclusive prefix
    if (f0) gPerm[b * S_LEN + base]      = i0;
    if (f1) gPerm[b * S_LEN + base + f0] = i1;
    if (threadIdx.x == 1023) gN[b] = base + val;
}

// ---------------- gather + pre-split: compacted K/V -> bf16 hi/lo ----------------
// 256 threads: each thread does one float4 (16B) of one row; 16 rows/block.
// Rows beyond the padded key count are never read by the main kernel -> skipped.
__global__ __launch_bounds__(256)
void presplit_kernel(const float* __restrict__ K, const float* __restrict__ V)
{
    const int g   = blockIdx.x * 16 + (threadIdx.x >> 4);   // global row (b,h,r)
    const int c4  = threadIdx.x & 15;                       // float4 column
    const int bh  = g / S_LEN;
    const int r   = g - bh * S_LEN;
    const int b   = bh / H_HEADS;
    const int nvalid = gN[b];
    const int padrows = (nvalid + BK - 1) & ~(BK - 1);
    if (r >= padrows) return;

    const size_t dsti = (size_t)g * 16 + c4;                // uint2 index
    uint2* Khi2 = (uint2*)gKhi; uint2* Klo2 = (uint2*)gKlo;
    uint2* Vhi2 = (uint2*)gVhi; uint2* Vlo2 = (uint2*)gVlo;

    if (r < nvalid) {
        const int src = gPerm[b * S_LEN + r];
        const size_t srci = ((size_t)bh * S_LEN + src) * 16 + c4;
        float4 k = ((const float4*)K)[srci];
        uint32_t h0, l0, h1, l1;
        split2(k.x, k.y, h0, l0);
        split2(k.z, k.w, h1, l1);
        Khi2[dsti] = make_uint2(h0, h1);
        Klo2[dsti] = make_uint2(l0, l1);
        float4 v = ((const float4*)V)[srci];
        split2(v.x, v.y, h0, l0);
        split2(v.z, v.w, h1, l1);
        Vhi2[dsti] = make_uint2(h0, h1);
        Vlo2[dsti] = make_uint2(l0, l1);
    } else {
        uint2 z = make_uint2(0u, 0u);
        Khi2[dsti] = z; Klo2[dsti] = z;
        Vhi2[dsti] = z; Vlo2[dsti] = z;
    }
}

// ---------------- main kernel ----------------
__global__ __launch_bounds__(128, 4)
void flash_attn_hmma(const float* __restrict__ Q, float* __restrict__ O)
{
    extern __shared__ __align__(16) char sm[];
    const uint32_t sb = smem_u32(sm);
    float* smask = (float*)(sm + MASK_OFF);            // [32] pad bias (last tile only)

    const int tid   = threadIdx.x;
    const int wid   = tid >> 5;
    const int lane  = tid & 31;
    const int group = lane >> 2;
    const int tig   = lane & 3;
    const int lg    = lane >> 3;      // 0..3: ldmatrix lane-group
    const int lr    = lane & 7;

    const int qt = blockIdx.x & (S_LEN / BM - 1);      // 32 q-tiles/head
    const int bh = blockIdx.x >> 5;
    const int b  = bh / H_HEADS;

    const int nvalid = gN[b];
    const int ntiles = (nvalid + BK - 1) / BK;

    const size_t kvbase = (size_t)bh * S_LEN * DH;
    const __nv_bfloat16* garr[4] = { gKhi + kvbase, gKlo + kvbase,
                                     gVhi + kvbase, gVlo + kvbase };

    // ---- Q fragments (hi/lo), loaded once ----
    const float QSC = 0.125f * 1.44269504088896340736f;   // 1/sqrt(64) * log2(e)
    uint32_t qhi[4][4], qlo[4][4];
    {
        const float* Qb = Q + ((size_t)bh * S_LEN + (size_t)qt * BM + wid * 16) * DH;
        const int r0 = group, r1 = group + 8;
#pragma unroll
        for (int k = 0; k < 4; k++) {
            int c0 = 16 * k + 2 * tig, c1 = c0 + 8;
            float2 f;
            f = *(const float2*)(Qb + r0 * DH + c0);
            split2(f.x * QSC, f.y * QSC, qhi[k][0], qlo[k][0]);
            f = *(const float2*)(Qb + r1 * DH + c0);
            split2(f.x * QSC, f.y * QSC, qhi[k][1], qlo[k][1]);
            f = *(const float2*)(Qb + r0 * DH + c1);
            split2(f.x * QSC, f.y * QSC, qhi[k][2], qlo[k][2]);
            f = *(const float2*)(Qb + r1 * DH + c1);
            split2(f.x * QSC, f.y * QSC, qhi[k][3], qlo[k][3]);
        }
    }

    float o[8][4];
#pragma unroll
    for (int j = 0; j < 8; j++)
#pragma unroll
        for (int i = 0; i < 4; i++) o[j][i] = 0.f;
    float l0 = 0.f, l1 = 0.f;

    const float CSH = 12.0f * 1.44269504088896340736f;  // static shift, exp2 domain

    // ldmatrix.x4 per-lane byte offsets (within an array tile)
    const uint32_t koff = (uint32_t)(((8 * (lg >> 1) + lr) * SROW + 8 * (lg & 1)) * 2);
    const uint32_t voff = (uint32_t)(((8 * (lg & 1) + lr) * SROW + 8 * (lg >> 1)) * 2);

    // ---- pad-bias for the final tile, written once ----
    if (tid < BK)
        smask[tid] = ((ntiles - 1) * BK + tid < nvalid) ? 0.f : -3.0e38f;

    // ---- stage tile 0 (8 cp.async per thread: 2 per array) ----
#pragma unroll
    for (int arr = 0; arr < 4; arr++) {
#pragma unroll
        for (int ii = 0; ii < 2; ii++) {
            int idx = tid + 128 * ii;                 // 16B-chunk index 0..255
            int row = idx >> 3, ch = idx & 7;
            cp16(sb + arr * ARR_BYTES + row * 144 + ch * 16,
                 garr[arr] + row * 64 + ch * 8);
        }
    }
    CP_COMMIT();

    for (int t = 0; t < ntiles; t++) {
        const int buf = t & 1;
        CP_WAIT0();
        __syncthreads();

        // ---- prefetch tile t+1 into buf^1 ----
        if (t + 1 < ntiles) {
            const int nb = buf ^ 1;
            const size_t toff = (size_t)(t + 1) * BK * DH;
#pragma unroll
            for (int arr = 0; arr < 4; arr++) {
#pragma unroll
                for (int ii = 0; ii < 2; ii++) {
                    int idx = tid + 128 * ii;
                    int row = idx >> 3, ch = idx & 7;
                    cp16(sb + nb * BUF_BYTES + arr * ARR_BYTES + row * 144 + ch * 16,
                         garr[arr] + toff + row * 64 + ch * 8);
                }
            }
        }
        CP_COMMIT();

        const uint32_t aKhi = sb + buf * BUF_BYTES;
        const uint32_t aKlo = aKhi + ARR_BYTES;
        const uint32_t aVhi = aKlo + ARR_BYTES;
        const uint32_t aVlo = aVhi + ARR_BYTES;
        const bool last = (t == ntiles - 1);

        float s[4][4];

        // GEMM1 for one key-16-block jp (0..1): S[:, 16jp..16jp+15]
#define GEMM1_JP(jp)                                                                  \
        do {                                                                          \
            _Pragma("unroll")                                                         \
            for (int i = 0; i < 4; i++) { s[2*(jp)][i] = 0.f; s[2*(jp)+1][i] = 0.f; } \
            uint32_t jb = koff + (uint32_t)(16 * (jp) * SROW * 2);                    \
            _Pragma("unroll")                                                         \
            for (int k = 0; k < 4; k++) {                                             \
                uint32_t boff = jb + (uint32_t)(16 * k * 2);                          \
                uint32_t h0, h1, h2, h3, x0, x1, x2, x3;                              \
                ldsm_x4(aKhi + boff, h0, h1, h2, h3);                                 \
                ldsm_x4(aKlo + boff, x0, x1, x2, x3);                                 \
                MMA_BF16(s[2*(jp)],   qhi[k][0], qhi[k][1], qhi[k][2], qhi[k][3], h0, h1); \
                MMA_BF16(s[2*(jp)+1], qhi[k][0], qhi[k][1], qhi[k][2], qhi[k][3], h2, h3); \
                MMA_BF16(s[2*(jp)],   qhi[k][0], qhi[k][1], qhi[k][2], qhi[k][3], x0, x1); \
                MMA_BF16(s[2*(jp)+1], qhi[k][0], qhi[k][1], qhi[k][2], qhi[k][3], x2, x3); \
                MMA_BF16(s[2*(jp)],   qlo[k][0], qlo[k][1], qlo[k][2], qlo[k][3], h0, h1); \
                MMA_BF16(s[2*(jp)+1], qlo[k][0], qlo[k][1], qlo[k][2], qlo[k][3], h2, h3); \
            }                                                                         \
        } while (0)

        GEMM1_JP(0);

#pragma unroll
        for (int k = 0; k < 2; k++) {
            // ---- softmax for key-step k (keys 16k..16k+15) ----
            uint32_t phi[4], plo[4];
            {
                float b00, b01, b10, b11;
                if (last) {
                    b00 = smask[16 * k + 2 * tig]         - CSH;
                    b01 = smask[16 * k + 2 * tig + 1]     - CSH;
                    b10 = smask[16 * k + 8 + 2 * tig]     - CSH;
                    b11 = smask[16 * k + 8 + 2 * tig + 1] - CSH;
                } else {
                    b00 = b01 = b10 = b11 = -CSH;
                }
                float p00 = fast_exp2(s[2*k][0] + b00);
                float p01 = fast_exp2(s[2*k][1] + b01);
                float p02 = fast_exp2(s[2*k][2] + b00);
                float p03 = fast_exp2(s[2*k][3] + b01);
                float p10 = fast_exp2(s[2*k+1][0] + b10);
                float p11 = fast_exp2(s[2*k+1][1] + b11);
                float p12 = fast_exp2(s[2*k+1][2] + b10);
                float p13 = fast_exp2(s[2*k+1][3] + b11);
                l0 += (p00 + p01) + (p10 + p11);
                l1 += (p02 + p03) + (p12 + p13);
                split2(p00, p01, phi[0], plo[0]);
                split2(p02, p03, phi[1], plo[1]);
                split2(p10, p11, phi[2], plo[2]);
                split2(p12, p13, phi[3], plo[3]);
            }

            // ---- GEMM1 for the second key block overlaps the softmax chains ----
            if (k == 0) GEMM1_JP(1);

            // ---- GEMM2 step k: O += P[:,16k..16k+15] x V[16k..16k+15, :] ----
#pragma unroll
            for (int jp = 0; jp < 4; jp++) {
                uint32_t boff = voff + (uint32_t)(16 * jp * 2)
                              + (uint32_t)(16 * k * SROW * 2);
                uint32_t h0, h1, h2, h3, x0, x1, x2, x3;
                ldsm_x4t(aVhi + boff, h0, h1, h2, h3);
                ldsm_x4t(aVlo + boff, x0, x1, x2, x3);
                MMA_BF16(o[2*jp],   phi[0], phi[1], phi[2], phi[3], h0, h1);
                MMA_BF16(o[2*jp+1], phi[0], phi[1], phi[2], phi[3], h2, h3);
                MMA_BF16(o[2*jp],   phi[0], phi[1], phi[2], phi[3], x0, x1);
                MMA_BF16(o[2*jp+1], phi[0], phi[1], phi[2], phi[3], x2, x3);
                MMA_BF16(o[2*jp],   plo[0], plo[1], plo[2], plo[3], h0, h1);
                MMA_BF16(o[2*jp+1], plo[0], plo[1], plo[2], plo[3], h2, h3);
            }
        }
#undef GEMM1_JP
    }

    // ---- epilogue ----
    l0 += __shfl_xor_sync(0xFFFFFFFFu, l0, 1);
    l0 += __shfl_xor_sync(0xFFFFFFFFu, l0, 2);
    l1 += __shfl_xor_sync(0xFFFFFFFFu, l1, 1);
    l1 += __shfl_xor_sync(0xFFFFFFFFu, l1, 2);
    float inv0 = 1.f / fmaxf(l0, 1e-35f);
    float inv1 = 1.f / fmaxf(l1, 1e-35f);

    float* Ob = O + ((size_t)bh * S_LEN + (size_t)qt * BM + wid * 16) * DH;
    const int r0 = group, r1 = group + 8;
#pragma unroll
    for (int j = 0; j < 8; j++) {
        int c = 8 * j + 2 * tig;
        *(float2*)(Ob + r0 * DH + c) = make_float2(o[j][0] * inv0, o[j][1] * inv0);
        *(float2*)(Ob + r1 * DH + c) = make_float2(o[j][2] * inv1, o[j][3] * inv1);
    }
}

extern "C" void kernel_launch(void* const* d_in, const int* in_sizes, int n_in,
                              void* d_out, int out_size)
{
    (void)in_sizes; (void)n_in; (void)out_size;
    const float* Q = (const float*)d_in[0];
    const float* K = (const float*)d_in[1];
    const float* V = (const float*)d_in[2];
    const void*  M = d_in[3];
    float* O = (float*)d_out;

    static int smem_set = 0;
    if (!smem_set) {
        cudaFuncSetAttribute(flash_attn_hmma,
                             cudaFuncAttributeMaxDynamicSharedMemorySize, SMEM_BYTES);
        smem_set = 1;
    }

    compact_kernel<<<B_BATCH, 1024>>>(M);
    presplit_kernel<<<B_BATCH * H_HEADS * S_LEN / 16, 256>>>(K, V);
    flash_attn_hmma<<<B_BATCH * H_HEADS * (S_LEN / BM), 128, SMEM_BYTES>>>(Q, O);
}